// round 1
// baseline (speedup 1.0000x reference)
#include <cuda_runtime.h>
#include <math.h>

#define T_TOK   4096
#define HIDDEN_ 4096
#define NH      32
#define KVH_    8
#define HD      128
#define SEQ     1024
#define NB      4
#define ROT_    64
#define QKV_N   (NH*HD + 2*KVH_*HD)   /* 6144 */
#define NUM_SLOTS_ 8192

// Scratch (static device globals — no allocation at runtime)
__device__ float g_qkv[(size_t)T_TOK * QKV_N];      // 96 MB
__device__ float g_attn[(size_t)T_TOK * NH * HD];   // 64 MB

// ---------------------------------------------------------------------------
// SGEMM (NT): C[M,N] = A[M,K] * B[N,K]^T, all row-major, dims divisible by 128/16
// 128x128 block tile, BK=16, 256 threads, 8x8 micro-tile per thread.
// ---------------------------------------------------------------------------
__global__ void __launch_bounds__(256) sgemm_nt(const float* __restrict__ A,
                                                const float* __restrict__ B,
                                                float* __restrict__ C,
                                                int M, int N, int K) {
    __shared__ float As[16][128];
    __shared__ float Bs[16][128];

    const int bm = blockIdx.y * 128;
    const int bn = blockIdx.x * 128;
    const int tid = threadIdx.x;
    const int ty = tid >> 4;    // 0..15
    const int tx = tid & 15;    // 0..15

    float acc[8][8];
#pragma unroll
    for (int i = 0; i < 8; i++)
#pragma unroll
        for (int j = 0; j < 8; j++) acc[i][j] = 0.f;

    for (int k0 = 0; k0 < K; k0 += 16) {
#pragma unroll
        for (int l = 0; l < 2; l++) {
            int i  = tid + l * 256;          // 0..511
            int r  = i >> 2;                 // 0..127
            int c4 = (i & 3) << 2;           // 0,4,8,12
            float4 va = *(const float4*)(A + (size_t)(bm + r) * K + k0 + c4);
            As[c4 + 0][r] = va.x; As[c4 + 1][r] = va.y;
            As[c4 + 2][r] = va.z; As[c4 + 3][r] = va.w;
            float4 vb = *(const float4*)(B + (size_t)(bn + r) * K + k0 + c4);
            Bs[c4 + 0][r] = vb.x; Bs[c4 + 1][r] = vb.y;
            Bs[c4 + 2][r] = vb.z; Bs[c4 + 3][r] = vb.w;
        }
        __syncthreads();
#pragma unroll
        for (int kk = 0; kk < 16; kk++) {
            float a[8], b[8];
            *(float4*)(a)     = *(float4*)&As[kk][ty * 8];
            *(float4*)(a + 4) = *(float4*)&As[kk][ty * 8 + 4];
            *(float4*)(b)     = *(float4*)&Bs[kk][tx * 8];
            *(float4*)(b + 4) = *(float4*)&Bs[kk][tx * 8 + 4];
#pragma unroll
            for (int i = 0; i < 8; i++)
#pragma unroll
                for (int j = 0; j < 8; j++)
                    acc[i][j] += a[i] * b[j];
        }
        __syncthreads();
    }

#pragma unroll
    for (int i = 0; i < 8; i++) {
        float4* cp = (float4*)(C + (size_t)(bm + ty * 8 + i) * N + bn + tx * 8);
        cp[0] = make_float4(acc[i][0], acc[i][1], acc[i][2], acc[i][3]);
        cp[1] = make_float4(acc[i][4], acc[i][5], acc[i][6], acc[i][7]);
    }
}

// ---------------------------------------------------------------------------
// RoPE (q and k in-place in g_qkv) + scatter k (roped) / v into cache outputs.
// One block per token, 256 threads.
// ---------------------------------------------------------------------------
__global__ void __launch_bounds__(256) rope_scatter(const float* __restrict__ cosb,
                                                    const float* __restrict__ sinb,
                                                    const int* __restrict__ slots,
                                                    float* __restrict__ kcache,
                                                    float* __restrict__ vcache) {
    const int t = blockIdx.x;
    const int tid = threadIdx.x;
    float* row = g_qkv + (size_t)t * QKV_N;

    __shared__ float cs[ROT_], sn[ROT_];
    if (tid < ROT_) {
        cs[tid] = cosb[t * ROT_ + tid];
        sn[tid] = sinb[t * ROT_ + tid];
    }
    __syncthreads();

    // q: 32 heads * 64 pairs = 2048 pairs
#pragma unroll
    for (int l = 0; l < 8; l++) {
        int p  = tid + l * 256;
        int hh = p >> 6, r = p & 63;
        float x1 = row[hh * HD + r];
        float x2 = row[hh * HD + 64 + r];
        row[hh * HD + r]      = x1 * cs[r] - x2 * sn[r];
        row[hh * HD + 64 + r] = x1 * sn[r] + x2 * cs[r];
    }

    const int slot = slots[t];
    // k: 8 heads * 64 pairs = 512 pairs (rope in place + write to cache)
#pragma unroll
    for (int l = 0; l < 2; l++) {
        int p  = tid + l * 256;
        int kh = p >> 6, r = p & 63;
        size_t o = (size_t)NH * HD + kh * HD;
        float x1 = row[o + r];
        float x2 = row[o + 64 + r];
        float y1 = x1 * cs[r] - x2 * sn[r];
        float y2 = x1 * sn[r] + x2 * cs[r];
        row[o + r]      = y1;
        row[o + 64 + r] = y2;
        kcache[(size_t)slot * KVH_ * HD + kh * HD + r]      = y1;
        kcache[(size_t)slot * KVH_ * HD + kh * HD + 64 + r] = y2;
    }
    // v: 1024 floats copy
#pragma unroll
    for (int l = 0; l < 4; l++) {
        int idx = tid + l * 256;
        vcache[(size_t)slot * KVH_ * HD + idx] = row[(size_t)(NH + KVH_) * HD + idx];
    }
}

// ---------------------------------------------------------------------------
// Flash attention (causal, GQA group=4): BQ=BKV=64, 256 threads.
// Q,K stored TRANSPOSED in shared with stride 65 (bank-conflict-free score loop).
// grid: (SEQ/64, NH, NB)
// ---------------------------------------------------------------------------
__global__ void __launch_bounds__(256) flash_attn(float* __restrict__ O) {
    extern __shared__ float sm[];
    float* Qt   = sm;                 // [128][65] transposed: Qt[d*65 + r]
    float* Kt   = Qt + 128 * 65;      // [128][65]
    float* Vs   = Kt + 128 * 65;      // [64][128] row-major
    float* Ps   = Vs + 64 * 128;      // [64][64]
    float* rowm = Ps + 64 * 64;       // [64]
    float* rowl = rowm + 64;          // [64]
    float* rowa = rowl + 64;          // [64]
    float* red  = rowa + 64;          // [64][16]

    const int q0  = blockIdx.x * 64;
    const int h   = blockIdx.y;
    const int b   = blockIdx.z;
    const int kvh = h >> 2;
    const int tid = threadIdx.x;
    const int ty  = tid >> 4, tx = tid & 15;
    const int ty4 = ty * 4,  tx4 = tx * 4;
    const float scale = 0.08838834764831845f;  // 128^-0.5

    // Load Q tile transposed
#pragma unroll
    for (int l = 0; l < 8; l++) {
        int i4 = tid + l * 256;          // 0..2047 (float4 granules)
        int r  = i4 >> 5;                // 0..63
        int c  = (i4 & 31) << 2;         // 0..124
        float4 v = *(const float4*)&g_qkv[(size_t)(b * SEQ + q0 + r) * QKV_N + h * HD + c];
        Qt[(c + 0) * 65 + r] = v.x; Qt[(c + 1) * 65 + r] = v.y;
        Qt[(c + 2) * 65 + r] = v.z; Qt[(c + 3) * 65 + r] = v.w;
    }
    if (tid < 64) { rowm[tid] = -1e30f; rowl[tid] = 0.f; }

    float acc[4][8];
#pragma unroll
    for (int i = 0; i < 4; i++)
#pragma unroll
        for (int c = 0; c < 8; c++) acc[i][c] = 0.f;

    const int ntiles = blockIdx.x + 1;
    for (int kt = 0; kt < ntiles; kt++) {
        const int kv0 = kt * 64;
        __syncthreads();   // protect Kt/Vs/Ps from prior iteration readers

        // Load K (transposed) and V (row-major)
#pragma unroll
        for (int l = 0; l < 8; l++) {
            int i4 = tid + l * 256;
            int r  = i4 >> 5;
            int c  = (i4 & 31) << 2;
            size_t base = (size_t)(b * SEQ + kv0 + r) * QKV_N;
            float4 kv = *(const float4*)&g_qkv[base + NH * HD + kvh * HD + c];
            Kt[(c + 0) * 65 + r] = kv.x; Kt[(c + 1) * 65 + r] = kv.y;
            Kt[(c + 2) * 65 + r] = kv.z; Kt[(c + 3) * 65 + r] = kv.w;
            float4 vv = *(const float4*)&g_qkv[base + (NH + KVH_) * HD + kvh * HD + c];
            *(float4*)&Vs[r * 128 + c] = vv;
        }
        __syncthreads();

        // Scores: 4x4 micro-tile, rows q0+ty4.., cols kv0+tx4..
        float s[4][4];
#pragma unroll
        for (int i = 0; i < 4; i++)
#pragma unroll
            for (int j = 0; j < 4; j++) s[i][j] = 0.f;

#pragma unroll 4
        for (int d = 0; d < 128; d++) {
            float a0 = Qt[d * 65 + ty4 + 0];
            float a1 = Qt[d * 65 + ty4 + 1];
            float a2 = Qt[d * 65 + ty4 + 2];
            float a3 = Qt[d * 65 + ty4 + 3];
            float b0 = Kt[d * 65 + tx4 + 0];
            float b1 = Kt[d * 65 + tx4 + 1];
            float b2 = Kt[d * 65 + tx4 + 2];
            float b3 = Kt[d * 65 + tx4 + 3];
            s[0][0] += a0 * b0; s[0][1] += a0 * b1; s[0][2] += a0 * b2; s[0][3] += a0 * b3;
            s[1][0] += a1 * b0; s[1][1] += a1 * b1; s[1][2] += a1 * b2; s[1][3] += a1 * b3;
            s[2][0] += a2 * b0; s[2][1] += a2 * b1; s[2][2] += a2 * b2; s[2][3] += a2 * b3;
            s[3][0] += a3 * b0; s[3][1] += a3 * b1; s[3][2] += a3 * b2; s[3][3] += a3 * b3;
        }

        // scale + causal mask + per-thread row max partials
#pragma unroll
        for (int i = 0; i < 4; i++) {
            int qi = q0 + ty4 + i;
            float mx = -1e30f;
#pragma unroll
            for (int j = 0; j < 4; j++) {
                int kj = kv0 + tx4 + j;
                s[i][j] = (kj <= qi) ? s[i][j] * scale : -1e30f;
                mx = fmaxf(mx, s[i][j]);
            }
            red[(ty4 + i) * 16 + tx] = mx;
        }
        __syncthreads();

        if (tid < 64) {
            float m  = rowm[tid];
            float mt = -1e30f;
#pragma unroll
            for (int x = 0; x < 16; x++) mt = fmaxf(mt, red[tid * 16 + x]);
            float mn = fmaxf(m, mt);
            float al = __expf(m - mn);
            rowa[tid] = al;
            rowl[tid] *= al;
            rowm[tid] = mn;
        }
        __syncthreads();

        // exp, store P, row-sum partials; rescale accumulators
#pragma unroll
        for (int i = 0; i < 4; i++) {
            int r = ty4 + i;
            float m = rowm[r];
            float sum = 0.f;
#pragma unroll
            for (int j = 0; j < 4; j++) {
                float p = __expf(s[i][j] - m);
                Ps[r * 64 + tx4 + j] = p;
                sum += p;
            }
            red[r * 16 + tx] = sum;
            float al = rowa[r];
#pragma unroll
            for (int c = 0; c < 8; c++) acc[i][c] *= al;
        }
        __syncthreads();

        if (tid < 64) {
            float sum = 0.f;
#pragma unroll
            for (int x = 0; x < 16; x++) sum += red[tid * 16 + x];
            rowl[tid] += sum;
        }

        // PV: thread owns cols [tx4, tx4+4) and [64+tx4, 64+tx4+4)
#pragma unroll 2
        for (int j = 0; j < 64; j++) {
            float p0 = Ps[(ty4 + 0) * 64 + j];
            float p1 = Ps[(ty4 + 1) * 64 + j];
            float p2 = Ps[(ty4 + 2) * 64 + j];
            float p3 = Ps[(ty4 + 3) * 64 + j];
            float4 va = *(float4*)&Vs[j * 128 + tx4];
            float4 vb = *(float4*)&Vs[j * 128 + 64 + tx4];
            acc[0][0] += p0 * va.x; acc[0][1] += p0 * va.y; acc[0][2] += p0 * va.z; acc[0][3] += p0 * va.w;
            acc[1][0] += p1 * va.x; acc[1][1] += p1 * va.y; acc[1][2] += p1 * va.z; acc[1][3] += p1 * va.w;
            acc[2][0] += p2 * va.x; acc[2][1] += p2 * va.y; acc[2][2] += p2 * va.z; acc[2][3] += p2 * va.w;
            acc[3][0] += p3 * va.x; acc[3][1] += p3 * va.y; acc[3][2] += p3 * va.z; acc[3][3] += p3 * va.w;
            acc[0][4] += p0 * vb.x; acc[0][5] += p0 * vb.y; acc[0][6] += p0 * vb.z; acc[0][7] += p0 * vb.w;
            acc[1][4] += p1 * vb.x; acc[1][5] += p1 * vb.y; acc[1][6] += p1 * vb.z; acc[1][7] += p1 * vb.w;
            acc[2][4] += p2 * vb.x; acc[2][5] += p2 * vb.y; acc[2][6] += p2 * vb.z; acc[2][7] += p2 * vb.w;
            acc[3][4] += p3 * vb.x; acc[3][5] += p3 * vb.y; acc[3][6] += p3 * vb.z; acc[3][7] += p3 * vb.w;
        }
    }
    __syncthreads();

    // Normalize and store
#pragma unroll
    for (int i = 0; i < 4; i++) {
        int r = ty4 + i;
        float inv = 1.f / rowl[r];
        size_t obase = (size_t)(b * SEQ + q0 + r) * ((size_t)NH * HD) + h * HD;
        *(float4*)&O[obase + tx4] =
            make_float4(acc[i][0] * inv, acc[i][1] * inv, acc[i][2] * inv, acc[i][3] * inv);
        *(float4*)&O[obase + 64 + tx4] =
            make_float4(acc[i][4] * inv, acc[i][5] * inv, acc[i][6] * inv, acc[i][7] * inv);
    }
}

// ---------------------------------------------------------------------------
extern "C" void kernel_launch(void* const* d_in, const int* in_sizes, int n_in,
                              void* d_out, int out_size) {
    const float* hidden = (const float*)d_in[0];
    const float* cosb   = (const float*)d_in[1];
    const float* sinb   = (const float*)d_in[2];
    const float* w_qkv  = (const float*)d_in[3];
    const float* w_o    = (const float*)d_in[4];
    const float* kc_in  = (const float*)d_in[5];
    const float* vc_in  = (const float*)d_in[6];
    const int*   slots  = (const int*)d_in[7];
    // d_in[8] = seq_len (fixed at 1024 for this problem)

    float* out    = (float*)d_out;
    float* kc_out = out + (size_t)T_TOK * HIDDEN_;
    float* vc_out = kc_out + (size_t)NUM_SLOTS_ * KVH_ * HD;

    float *qkv, *attn;
    cudaGetSymbolAddress((void**)&qkv, g_qkv);
    cudaGetSymbolAddress((void**)&attn, g_attn);

    const size_t cache_bytes = sizeof(float) * (size_t)NUM_SLOTS_ * KVH_ * HD;
    cudaMemcpyAsync(kc_out, kc_in, cache_bytes, cudaMemcpyDeviceToDevice);
    cudaMemcpyAsync(vc_out, vc_in, cache_bytes, cudaMemcpyDeviceToDevice);

    // QKV projection: [4096,4096] x [6144,4096]^T
    sgemm_nt<<<dim3(QKV_N / 128, T_TOK / 128), 256>>>(hidden, w_qkv, qkv,
                                                      T_TOK, QKV_N, HIDDEN_);
    // RoPE + cache scatter
    rope_scatter<<<T_TOK, 256>>>(cosb, sinb, slots, kc_out, vc_out);

    // Flash attention
    int smem = (128 * 65 * 2 + 64 * 128 + 64 * 64 + 64 * 3 + 64 * 16) * sizeof(float);
    cudaFuncSetAttribute(flash_attn, cudaFuncAttributeMaxDynamicSharedMemorySize, smem);
    flash_attn<<<dim3(SEQ / 64, NH, NB), 256, smem>>>(attn);

    // Output projection: [4096,4096] x [4096,4096]^T
    sgemm_nt<<<dim3(HIDDEN_ / 128, T_TOK / 128), 256>>>(attn, w_o, out,
                                                        T_TOK, HIDDEN_, HIDDEN_);
}

// round 2
// speedup vs baseline: 1.0002x; 1.0002x over previous
#include <cuda_runtime.h>
#include <math.h>

#define T_TOK   4096
#define HIDDEN_ 4096
#define NH      32
#define KVH_    8
#define HD      128
#define SEQ     1024
#define NB      4
#define ROT_    64
#define QKV_N   (NH*HD + 2*KVH_*HD)   /* 6144 */
#define NUM_SLOTS_ 8192

// Scratch (static device globals — no allocation at runtime)
__device__ float g_qkv[(size_t)T_TOK * QKV_N];      // 96 MB
__device__ float g_attn[(size_t)T_TOK * NH * HD];   // 64 MB

// ---------------------------------------------------------------------------
// SGEMM (NT): C[M,N] = A[M,K] * B[N,K]^T, all row-major, dims divisible by 128/16
// 128x128 block tile, BK=16, 256 threads, 8x8 micro-tile per thread.
// ---------------------------------------------------------------------------
__global__ void __launch_bounds__(256) sgemm_nt(const float* __restrict__ A,
                                                const float* __restrict__ B,
                                                float* __restrict__ C,
                                                int M, int N, int K) {
    __shared__ float As[16][128];
    __shared__ float Bs[16][128];

    const int bm = blockIdx.y * 128;
    const int bn = blockIdx.x * 128;
    const int tid = threadIdx.x;
    const int ty = tid >> 4;    // 0..15
    const int tx = tid & 15;    // 0..15

    float acc[8][8];
#pragma unroll
    for (int i = 0; i < 8; i++)
#pragma unroll
        for (int j = 0; j < 8; j++) acc[i][j] = 0.f;

    for (int k0 = 0; k0 < K; k0 += 16) {
#pragma unroll
        for (int l = 0; l < 2; l++) {
            int i  = tid + l * 256;          // 0..511
            int r  = i >> 2;                 // 0..127
            int c4 = (i & 3) << 2;           // 0,4,8,12
            float4 va = *(const float4*)(A + (size_t)(bm + r) * K + k0 + c4);
            As[c4 + 0][r] = va.x; As[c4 + 1][r] = va.y;
            As[c4 + 2][r] = va.z; As[c4 + 3][r] = va.w;
            float4 vb = *(const float4*)(B + (size_t)(bn + r) * K + k0 + c4);
            Bs[c4 + 0][r] = vb.x; Bs[c4 + 1][r] = vb.y;
            Bs[c4 + 2][r] = vb.z; Bs[c4 + 3][r] = vb.w;
        }
        __syncthreads();
#pragma unroll
        for (int kk = 0; kk < 16; kk++) {
            float a[8], b[8];
            *(float4*)(a)     = *(float4*)&As[kk][ty * 8];
            *(float4*)(a + 4) = *(float4*)&As[kk][ty * 8 + 4];
            *(float4*)(b)     = *(float4*)&Bs[kk][tx * 8];
            *(float4*)(b + 4) = *(float4*)&Bs[kk][tx * 8 + 4];
#pragma unroll
            for (int i = 0; i < 8; i++)
#pragma unroll
                for (int j = 0; j < 8; j++)
                    acc[i][j] += a[i] * b[j];
        }
        __syncthreads();
    }

#pragma unroll
    for (int i = 0; i < 8; i++) {
        float4* cp = (float4*)(C + (size_t)(bm + ty * 8 + i) * N + bn + tx * 8);
        cp[0] = make_float4(acc[i][0], acc[i][1], acc[i][2], acc[i][3]);
        cp[1] = make_float4(acc[i][4], acc[i][5], acc[i][6], acc[i][7]);
    }
}

// ---------------------------------------------------------------------------
// RoPE (q and k in-place in g_qkv) + scatter k (roped) / v into cache outputs.
// One block per token, 256 threads.
// ---------------------------------------------------------------------------
__global__ void __launch_bounds__(256) rope_scatter(const float* __restrict__ cosb,
                                                    const float* __restrict__ sinb,
                                                    const int* __restrict__ slots,
                                                    float* __restrict__ kcache,
                                                    float* __restrict__ vcache) {
    const int t = blockIdx.x;
    const int tid = threadIdx.x;
    float* row = g_qkv + (size_t)t * QKV_N;

    __shared__ float cs[ROT_], sn[ROT_];
    if (tid < ROT_) {
        cs[tid] = cosb[t * ROT_ + tid];
        sn[tid] = sinb[t * ROT_ + tid];
    }
    __syncthreads();

    // q: 32 heads * 64 pairs = 2048 pairs
#pragma unroll
    for (int l = 0; l < 8; l++) {
        int p  = tid + l * 256;
        int hh = p >> 6, r = p & 63;
        float x1 = row[hh * HD + r];
        float x2 = row[hh * HD + 64 + r];
        row[hh * HD + r]      = x1 * cs[r] - x2 * sn[r];
        row[hh * HD + 64 + r] = x1 * sn[r] + x2 * cs[r];
    }

    const int slot = slots[t];
    // k: 8 heads * 64 pairs = 512 pairs (rope in place + write to cache)
#pragma unroll
    for (int l = 0; l < 2; l++) {
        int p  = tid + l * 256;
        int kh = p >> 6, r = p & 63;
        size_t o = (size_t)NH * HD + kh * HD;
        float x1 = row[o + r];
        float x2 = row[o + 64 + r];
        float y1 = x1 * cs[r] - x2 * sn[r];
        float y2 = x1 * sn[r] + x2 * cs[r];
        row[o + r]      = y1;
        row[o + 64 + r] = y2;
        kcache[(size_t)slot * KVH_ * HD + kh * HD + r]      = y1;
        kcache[(size_t)slot * KVH_ * HD + kh * HD + 64 + r] = y2;
    }
    // v: 1024 floats copy
#pragma unroll
    for (int l = 0; l < 4; l++) {
        int idx = tid + l * 256;
        vcache[(size_t)slot * KVH_ * HD + idx] = row[(size_t)(NH + KVH_) * HD + idx];
    }
}

// ---------------------------------------------------------------------------
// Flash attention (causal, GQA group=4): BQ=BKV=64, 256 threads.
// Q,K stored TRANSPOSED in shared with stride 65 (bank-conflict-free score loop).
// grid: (SEQ/64, NH, NB)
// ---------------------------------------------------------------------------
__global__ void __launch_bounds__(256) flash_attn(float* __restrict__ O) {
    extern __shared__ float sm[];
    float* Qt   = sm;                 // [128][65] transposed: Qt[d*65 + r]
    float* Kt   = Qt + 128 * 65;      // [128][65]
    float* Vs   = Kt + 128 * 65;      // [64][128] row-major
    float* Ps   = Vs + 64 * 128;      // [64][64]
    float* rowm = Ps + 64 * 64;       // [64]
    float* rowl = rowm + 64;          // [64]
    float* rowa = rowl + 64;          // [64]
    float* red  = rowa + 64;          // [64][16]

    const int q0  = blockIdx.x * 64;
    const int h   = blockIdx.y;
    const int b   = blockIdx.z;
    const int kvh = h >> 2;
    const int tid = threadIdx.x;
    const int ty  = tid >> 4, tx = tid & 15;
    const int ty4 = ty * 4,  tx4 = tx * 4;
    const float scale = 0.08838834764831845f;  // 128^-0.5

    // Load Q tile transposed
#pragma unroll
    for (int l = 0; l < 8; l++) {
        int i4 = tid + l * 256;          // 0..2047 (float4 granules)
        int r  = i4 >> 5;                // 0..63
        int c  = (i4 & 31) << 2;         // 0..124
        float4 v = *(const float4*)&g_qkv[(size_t)(b * SEQ + q0 + r) * QKV_N + h * HD + c];
        Qt[(c + 0) * 65 + r] = v.x; Qt[(c + 1) * 65 + r] = v.y;
        Qt[(c + 2) * 65 + r] = v.z; Qt[(c + 3) * 65 + r] = v.w;
    }
    if (tid < 64) { rowm[tid] = -1e30f; rowl[tid] = 0.f; }

    float acc[4][8];
#pragma unroll
    for (int i = 0; i < 4; i++)
#pragma unroll
        for (int c = 0; c < 8; c++) acc[i][c] = 0.f;

    const int ntiles = blockIdx.x + 1;
    for (int kt = 0; kt < ntiles; kt++) {
        const int kv0 = kt * 64;
        __syncthreads();   // protect Kt/Vs/Ps from prior iteration readers

        // Load K (transposed) and V (row-major)
#pragma unroll
        for (int l = 0; l < 8; l++) {
            int i4 = tid + l * 256;
            int r  = i4 >> 5;
            int c  = (i4 & 31) << 2;
            size_t base = (size_t)(b * SEQ + kv0 + r) * QKV_N;
            float4 kv = *(const float4*)&g_qkv[base + NH * HD + kvh * HD + c];
            Kt[(c + 0) * 65 + r] = kv.x; Kt[(c + 1) * 65 + r] = kv.y;
            Kt[(c + 2) * 65 + r] = kv.z; Kt[(c + 3) * 65 + r] = kv.w;
            float4 vv = *(const float4*)&g_qkv[base + (NH + KVH_) * HD + kvh * HD + c];
            *(float4*)&Vs[r * 128 + c] = vv;
        }
        __syncthreads();

        // Scores: 4x4 micro-tile, rows q0+ty4.., cols kv0+tx4..
        float s[4][4];
#pragma unroll
        for (int i = 0; i < 4; i++)
#pragma unroll
            for (int j = 0; j < 4; j++) s[i][j] = 0.f;

#pragma unroll 4
        for (int d = 0; d < 128; d++) {
            float a0 = Qt[d * 65 + ty4 + 0];
            float a1 = Qt[d * 65 + ty4 + 1];
            float a2 = Qt[d * 65 + ty4 + 2];
            float a3 = Qt[d * 65 + ty4 + 3];
            float b0 = Kt[d * 65 + tx4 + 0];
            float b1 = Kt[d * 65 + tx4 + 1];
            float b2 = Kt[d * 65 + tx4 + 2];
            float b3 = Kt[d * 65 + tx4 + 3];
            s[0][0] += a0 * b0; s[0][1] += a0 * b1; s[0][2] += a0 * b2; s[0][3] += a0 * b3;
            s[1][0] += a1 * b0; s[1][1] += a1 * b1; s[1][2] += a1 * b2; s[1][3] += a1 * b3;
            s[2][0] += a2 * b0; s[2][1] += a2 * b1; s[2][2] += a2 * b2; s[2][3] += a2 * b3;
            s[3][0] += a3 * b0; s[3][1] += a3 * b1; s[3][2] += a3 * b2; s[3][3] += a3 * b3;
        }

        // scale + causal mask + per-thread row max partials
#pragma unroll
        for (int i = 0; i < 4; i++) {
            int qi = q0 + ty4 + i;
            float mx = -1e30f;
#pragma unroll
            for (int j = 0; j < 4; j++) {
                int kj = kv0 + tx4 + j;
                s[i][j] = (kj <= qi) ? s[i][j] * scale : -1e30f;
                mx = fmaxf(mx, s[i][j]);
            }
            red[(ty4 + i) * 16 + tx] = mx;
        }
        __syncthreads();

        if (tid < 64) {
            float m  = rowm[tid];
            float mt = -1e30f;
#pragma unroll
            for (int x = 0; x < 16; x++) mt = fmaxf(mt, red[tid * 16 + x]);
            float mn = fmaxf(m, mt);
            float al = __expf(m - mn);
            rowa[tid] = al;
            rowl[tid] *= al;
            rowm[tid] = mn;
        }
        __syncthreads();

        // exp, store P, row-sum partials; rescale accumulators
#pragma unroll
        for (int i = 0; i < 4; i++) {
            int r = ty4 + i;
            float m = rowm[r];
            float sum = 0.f;
#pragma unroll
            for (int j = 0; j < 4; j++) {
                float p = __expf(s[i][j] - m);
                Ps[r * 64 + tx4 + j] = p;
                sum += p;
            }
            red[r * 16 + tx] = sum;
            float al = rowa[r];
#pragma unroll
            for (int c = 0; c < 8; c++) acc[i][c] *= al;
        }
        __syncthreads();

        if (tid < 64) {
            float sum = 0.f;
#pragma unroll
            for (int x = 0; x < 16; x++) sum += red[tid * 16 + x];
            rowl[tid] += sum;
        }

        // PV: thread owns cols [tx4, tx4+4) and [64+tx4, 64+tx4+4)
#pragma unroll 2
        for (int j = 0; j < 64; j++) {
            float p0 = Ps[(ty4 + 0) * 64 + j];
            float p1 = Ps[(ty4 + 1) * 64 + j];
            float p2 = Ps[(ty4 + 2) * 64 + j];
            float p3 = Ps[(ty4 + 3) * 64 + j];
            float4 va = *(float4*)&Vs[j * 128 + tx4];
            float4 vb = *(float4*)&Vs[j * 128 + 64 + tx4];
            acc[0][0] += p0 * va.x; acc[0][1] += p0 * va.y; acc[0][2] += p0 * va.z; acc[0][3] += p0 * va.w;
            acc[1][0] += p1 * va.x; acc[1][1] += p1 * va.y; acc[1][2] += p1 * va.z; acc[1][3] += p1 * va.w;
            acc[2][0] += p2 * va.x; acc[2][1] += p2 * va.y; acc[2][2] += p2 * va.z; acc[2][3] += p2 * va.w;
            acc[3][0] += p3 * va.x; acc[3][1] += p3 * va.y; acc[3][2] += p3 * va.z; acc[3][3] += p3 * va.w;
            acc[0][4] += p0 * vb.x; acc[0][5] += p0 * vb.y; acc[0][6] += p0 * vb.z; acc[0][7] += p0 * vb.w;
            acc[1][4] += p1 * vb.x; acc[1][5] += p1 * vb.y; acc[1][6] += p1 * vb.z; acc[1][7] += p1 * vb.w;
            acc[2][4] += p2 * vb.x; acc[2][5] += p2 * vb.y; acc[2][6] += p2 * vb.z; acc[2][7] += p2 * vb.w;
            acc[3][4] += p3 * vb.x; acc[3][5] += p3 * vb.y; acc[3][6] += p3 * vb.z; acc[3][7] += p3 * vb.w;
        }
    }
    __syncthreads();

    // Normalize and store
#pragma unroll
    for (int i = 0; i < 4; i++) {
        int r = ty4 + i;
        float inv = 1.f / rowl[r];
        size_t obase = (size_t)(b * SEQ + q0 + r) * ((size_t)NH * HD) + h * HD;
        *(float4*)&O[obase + tx4] =
            make_float4(acc[i][0] * inv, acc[i][1] * inv, acc[i][2] * inv, acc[i][3] * inv);
        *(float4*)&O[obase + 64 + tx4] =
            make_float4(acc[i][4] * inv, acc[i][5] * inv, acc[i][6] * inv, acc[i][7] * inv);
    }
}

// ---------------------------------------------------------------------------
extern "C" void kernel_launch(void* const* d_in, const int* in_sizes, int n_in,
                              void* d_out, int out_size) {
    const float* hidden = (const float*)d_in[0];
    const float* cosb   = (const float*)d_in[1];
    const float* sinb   = (const float*)d_in[2];
    const float* w_qkv  = (const float*)d_in[3];
    const float* w_o    = (const float*)d_in[4];
    const float* kc_in  = (const float*)d_in[5];
    const float* vc_in  = (const float*)d_in[6];
    const int*   slots  = (const int*)d_in[7];
    // d_in[8] = seq_len (fixed at 1024 for this problem)

    float* out    = (float*)d_out;
    float* kc_out = out + (size_t)T_TOK * HIDDEN_;
    float* vc_out = kc_out + (size_t)NUM_SLOTS_ * KVH_ * HD;

    float *qkv, *attn;
    cudaGetSymbolAddress((void**)&qkv, g_qkv);
    cudaGetSymbolAddress((void**)&attn, g_attn);

    const size_t cache_bytes = sizeof(float) * (size_t)NUM_SLOTS_ * KVH_ * HD;
    cudaMemcpyAsync(kc_out, kc_in, cache_bytes, cudaMemcpyDeviceToDevice);
    cudaMemcpyAsync(vc_out, vc_in, cache_bytes, cudaMemcpyDeviceToDevice);

    // QKV projection: [4096,4096] x [6144,4096]^T
    sgemm_nt<<<dim3(QKV_N / 128, T_TOK / 128), 256>>>(hidden, w_qkv, qkv,
                                                      T_TOK, QKV_N, HIDDEN_);
    // RoPE + cache scatter
    rope_scatter<<<T_TOK, 256>>>(cosb, sinb, slots, kc_out, vc_out);

    // Flash attention
    int smem = (128 * 65 * 2 + 64 * 128 + 64 * 64 + 64 * 3 + 64 * 16) * sizeof(float);
    cudaFuncSetAttribute(flash_attn, cudaFuncAttributeMaxDynamicSharedMemorySize, smem);
    flash_attn<<<dim3(SEQ / 64, NH, NB), 256, smem>>>(attn);

    // Output projection: [4096,4096] x [4096,4096]^T
    sgemm_nt<<<dim3(HIDDEN_ / 128, T_TOK / 128), 256>>>(attn, w_o, out,
                                                        T_TOK, HIDDEN_, HIDDEN_);
}

// round 4
// speedup vs baseline: 2.3355x; 2.3351x over previous
#include <cuda_runtime.h>
#include <math.h>

#define T_TOK   4096
#define HIDDEN_ 4096
#define NH      32
#define KVH_    8
#define HD      128
#define SEQ     1024
#define NB      4
#define ROT_    64
#define QKV_N   (NH*HD + 2*KVH_*HD)   /* 6144 */
#define NUM_SLOTS_ 8192

// Scratch (static device globals — no allocation at runtime)
__device__ float g_qkv[(size_t)T_TOK * QKV_N];      // 96 MB
__device__ float g_attn[(size_t)T_TOK * NH * HD];   // 64 MB

// ---------------------------------------------------------------------------
// tf32 helpers
// ---------------------------------------------------------------------------
__device__ __forceinline__ unsigned f2tf32(float x) {
    unsigned r;
    asm("cvt.rna.tf32.f32 %0, %1;" : "=r"(r) : "f"(x));
    return r;
}

__device__ __forceinline__ unsigned smem_u32(const void* p) {
    return (unsigned)__cvta_generic_to_shared(p);
}

__device__ __forceinline__ void ldsm_x4(unsigned* r, unsigned addr) {
    asm volatile("ldmatrix.sync.aligned.m8n8.x4.shared.b16 {%0,%1,%2,%3}, [%4];"
                 : "=r"(r[0]), "=r"(r[1]), "=r"(r[2]), "=r"(r[3]) : "r"(addr));
}

__device__ __forceinline__ void ldsm_x2(unsigned* r, unsigned addr) {
    asm volatile("ldmatrix.sync.aligned.m8n8.x2.shared.b16 {%0,%1}, [%2];"
                 : "=r"(r[0]), "=r"(r[1]) : "r"(addr));
}

__device__ __forceinline__ void mma_tf32(float* d, const unsigned* a, const unsigned* b) {
    asm volatile(
        "mma.sync.aligned.m16n8k8.row.col.f32.tf32.tf32.f32 "
        "{%0,%1,%2,%3}, {%4,%5,%6,%7}, {%8,%9}, {%0,%1,%2,%3};"
        : "+f"(d[0]), "+f"(d[1]), "+f"(d[2]), "+f"(d[3])
        : "r"(a[0]), "r"(a[1]), "r"(a[2]), "r"(a[3]), "r"(b[0]), "r"(b[1]));
}

// ---------------------------------------------------------------------------
// tf32 GEMM (NT): C[M,N] = A[M,K] * B[N,K]^T. M,N % 128 == 0, K % 16 == 0.
// 128x128 block, BK=16, 256 threads = 8 warps (2m x 4n), 64x32 warp tiles.
// smem padded to stride 20 floats (conflict-free ldmatrix).
// ---------------------------------------------------------------------------
#define GS 20  // smem row stride (floats)

__global__ void __launch_bounds__(256, 2) tf32gemm_nt(const float* __restrict__ A,
                                                      const float* __restrict__ B,
                                                      float* __restrict__ C,
                                                      int M, int N, int K) {
    __shared__ unsigned As[128 * GS];
    __shared__ unsigned Bs[128 * GS];

    const int tid  = threadIdx.x;
    const int warp = tid >> 5, lane = tid & 31;
    const int wm = (warp >> 2) * 64;   // 0 or 64
    const int wn = (warp & 3) * 32;    // 0,32,64,96
    const int bm = blockIdx.y * 128;
    const int bn = blockIdx.x * 128;

    // ldmatrix per-lane source rows/cols (32-bit word units)
    const int a_row = (lane & 7) + ((lane >> 3) & 1) * 8;
    const int a_col = (lane >> 4) * 4;
    const int b_row = lane & 7;
    const int b_col = ((lane >> 3) & 1) * 4;

    unsigned as_base = smem_u32(As);
    unsigned bs_base = smem_u32(Bs);
    unsigned a_addr[4], b_addr[4];
#pragma unroll
    for (int i = 0; i < 4; i++)
        a_addr[i] = as_base + ((wm + 16 * i + a_row) * GS + a_col) * 4;
#pragma unroll
    for (int j = 0; j < 4; j++)
        b_addr[j] = bs_base + ((wn + 8 * j + b_row) * GS + b_col) * 4;

    // gmem tile loader mapping: 512 float4 per tile, 2 per thread
    const int gr0 = tid >> 2;          // 0..63  (rows tid>>2 and (tid+256)>>2)
    const int gc  = (tid & 3) * 4;     // 0,4,8,12

    float4 pa[2], pb[2];
    {
        const float* ap = A + (size_t)(bm + gr0) * K + gc;
        const float* bp = B + (size_t)(bn + gr0) * K + gc;
        pa[0] = *(const float4*)ap;
        pa[1] = *(const float4*)(ap + 64 * K);
        pb[0] = *(const float4*)bp;
        pb[1] = *(const float4*)(bp + 64 * K);
    }

    float acc[4][4][4];
#pragma unroll
    for (int i = 0; i < 4; i++)
#pragma unroll
        for (int j = 0; j < 4; j++)
#pragma unroll
            for (int c = 0; c < 4; c++) acc[i][j][c] = 0.f;

    for (int kt = 0; kt < K; kt += 16) {
        __syncthreads();
#pragma unroll
        for (int l = 0; l < 2; l++) {
            int r = gr0 + l * 64;
            unsigned* as = &As[r * GS + gc];
            as[0] = f2tf32(pa[l].x); as[1] = f2tf32(pa[l].y);
            as[2] = f2tf32(pa[l].z); as[3] = f2tf32(pa[l].w);
            unsigned* bs = &Bs[r * GS + gc];
            bs[0] = f2tf32(pb[l].x); bs[1] = f2tf32(pb[l].y);
            bs[2] = f2tf32(pb[l].z); bs[3] = f2tf32(pb[l].w);
        }
        __syncthreads();

        if (kt + 16 < K) {
            const float* ap = A + (size_t)(bm + gr0) * K + kt + 16 + gc;
            const float* bp = B + (size_t)(bn + gr0) * K + kt + 16 + gc;
            pa[0] = *(const float4*)ap;
            pa[1] = *(const float4*)(ap + 64 * K);
            pb[0] = *(const float4*)bp;
            pb[1] = *(const float4*)(bp + 64 * K);
        }

#pragma unroll
        for (int ks = 0; ks < 2; ks++) {
            unsigned bf[4][2];
#pragma unroll
            for (int j = 0; j < 4; j++) ldsm_x2(bf[j], b_addr[j] + ks * 32);
#pragma unroll
            for (int i = 0; i < 4; i++) {
                unsigned af[4];
                ldsm_x4(af, a_addr[i] + ks * 32);
#pragma unroll
                for (int j = 0; j < 4; j++) mma_tf32(acc[i][j], af, bf[j]);
            }
        }
    }

    // Epilogue: c0,c1 = (row g, cols 2q,2q+1); c2,c3 = row g+8
    const int g = lane >> 2;
    const int q2 = (lane & 3) * 2;
#pragma unroll
    for (int i = 0; i < 4; i++) {
#pragma unroll
        for (int j = 0; j < 4; j++) {
            int row = bm + wm + 16 * i + g;
            int col = bn + wn + 8 * j + q2;
            *(float2*)&C[(size_t)row * N + col] = make_float2(acc[i][j][0], acc[i][j][1]);
            *(float2*)&C[(size_t)(row + 8) * N + col] = make_float2(acc[i][j][2], acc[i][j][3]);
        }
    }
}

// ---------------------------------------------------------------------------
// RoPE (q and k in-place in g_qkv) + scatter k (roped) / v into cache outputs.
// ---------------------------------------------------------------------------
__global__ void __launch_bounds__(256) rope_scatter(const float* __restrict__ cosb,
                                                    const float* __restrict__ sinb,
                                                    const int* __restrict__ slots,
                                                    float* __restrict__ kcache,
                                                    float* __restrict__ vcache) {
    const int t = blockIdx.x;
    const int tid = threadIdx.x;
    float* row = g_qkv + (size_t)t * QKV_N;

    __shared__ float cs[ROT_], sn[ROT_];
    if (tid < ROT_) {
        cs[tid] = cosb[t * ROT_ + tid];
        sn[tid] = sinb[t * ROT_ + tid];
    }
    __syncthreads();

#pragma unroll
    for (int l = 0; l < 8; l++) {
        int p  = tid + l * 256;
        int hh = p >> 6, r = p & 63;
        float x1 = row[hh * HD + r];
        float x2 = row[hh * HD + 64 + r];
        row[hh * HD + r]      = x1 * cs[r] - x2 * sn[r];
        row[hh * HD + 64 + r] = x1 * sn[r] + x2 * cs[r];
    }

    const int slot = slots[t];
#pragma unroll
    for (int l = 0; l < 2; l++) {
        int p  = tid + l * 256;
        int kh = p >> 6, r = p & 63;
        size_t o = (size_t)NH * HD + kh * HD;
        float x1 = row[o + r];
        float x2 = row[o + 64 + r];
        float y1 = x1 * cs[r] - x2 * sn[r];
        float y2 = x1 * sn[r] + x2 * cs[r];
        row[o + r]      = y1;
        row[o + 64 + r] = y2;
        kcache[(size_t)slot * KVH_ * HD + kh * HD + r]      = y1;
        kcache[(size_t)slot * KVH_ * HD + kh * HD + 64 + r] = y2;
    }
#pragma unroll
    for (int l = 0; l < 4; l++) {
        int idx = tid + l * 256;
        vcache[(size_t)slot * KVH_ * HD + idx] = row[(size_t)(NH + KVH_) * HD + idx];
    }
}

// ---------------------------------------------------------------------------
// Flash attention (causal, GQA group=4): BQ=BKV=64, 256 threads. fp32 SIMT.
// ---------------------------------------------------------------------------
__global__ void __launch_bounds__(256) flash_attn(float* __restrict__ O) {
    extern __shared__ float sm[];
    float* Qt   = sm;                 // [128][65] transposed
    float* Kt   = Qt + 128 * 65;      // [128][65]
    float* Vs   = Kt + 128 * 65;      // [64][128]
    float* Ps   = Vs + 64 * 128;      // [64][64]
    float* rowm = Ps + 64 * 64;
    float* rowl = rowm + 64;
    float* rowa = rowl + 64;
    float* red  = rowa + 64;          // [64][16]

    const int q0  = blockIdx.x * 64;
    const int h   = blockIdx.y;
    const int b   = blockIdx.z;
    const int kvh = h >> 2;
    const int tid = threadIdx.x;
    const int ty  = tid >> 4, tx = tid & 15;
    const int ty4 = ty * 4,  tx4 = tx * 4;
    const float scale = 0.08838834764831845f;

#pragma unroll
    for (int l = 0; l < 8; l++) {
        int i4 = tid + l * 256;
        int r  = i4 >> 5;
        int c  = (i4 & 31) << 2;
        float4 v = *(const float4*)&g_qkv[(size_t)(b * SEQ + q0 + r) * QKV_N + h * HD + c];
        Qt[(c + 0) * 65 + r] = v.x; Qt[(c + 1) * 65 + r] = v.y;
        Qt[(c + 2) * 65 + r] = v.z; Qt[(c + 3) * 65 + r] = v.w;
    }
    if (tid < 64) { rowm[tid] = -1e30f; rowl[tid] = 0.f; }

    float acc[4][8];
#pragma unroll
    for (int i = 0; i < 4; i++)
#pragma unroll
        for (int c = 0; c < 8; c++) acc[i][c] = 0.f;

    const int ntiles = blockIdx.x + 1;
    for (int kt = 0; kt < ntiles; kt++) {
        const int kv0 = kt * 64;
        __syncthreads();

#pragma unroll
        for (int l = 0; l < 8; l++) {
            int i4 = tid + l * 256;
            int r  = i4 >> 5;
            int c  = (i4 & 31) << 2;
            size_t base = (size_t)(b * SEQ + kv0 + r) * QKV_N;
            float4 kv = *(const float4*)&g_qkv[base + NH * HD + kvh * HD + c];
            Kt[(c + 0) * 65 + r] = kv.x; Kt[(c + 1) * 65 + r] = kv.y;
            Kt[(c + 2) * 65 + r] = kv.z; Kt[(c + 3) * 65 + r] = kv.w;
            float4 vv = *(const float4*)&g_qkv[base + (NH + KVH_) * HD + kvh * HD + c];
            *(float4*)&Vs[r * 128 + c] = vv;
        }
        __syncthreads();

        float s[4][4];
#pragma unroll
        for (int i = 0; i < 4; i++)
#pragma unroll
            for (int j = 0; j < 4; j++) s[i][j] = 0.f;

#pragma unroll 4
        for (int d = 0; d < 128; d++) {
            float a0 = Qt[d * 65 + ty4 + 0];
            float a1 = Qt[d * 65 + ty4 + 1];
            float a2 = Qt[d * 65 + ty4 + 2];
            float a3 = Qt[d * 65 + ty4 + 3];
            float b0 = Kt[d * 65 + tx4 + 0];
            float b1 = Kt[d * 65 + tx4 + 1];
            float b2 = Kt[d * 65 + tx4 + 2];
            float b3 = Kt[d * 65 + tx4 + 3];
            s[0][0] += a0 * b0; s[0][1] += a0 * b1; s[0][2] += a0 * b2; s[0][3] += a0 * b3;
            s[1][0] += a1 * b0; s[1][1] += a1 * b1; s[1][2] += a1 * b2; s[1][3] += a1 * b3;
            s[2][0] += a2 * b0; s[2][1] += a2 * b1; s[2][2] += a2 * b2; s[2][3] += a2 * b3;
            s[3][0] += a3 * b0; s[3][1] += a3 * b1; s[3][2] += a3 * b2; s[3][3] += a3 * b3;
        }

#pragma unroll
        for (int i = 0; i < 4; i++) {
            int qi = q0 + ty4 + i;
            float mx = -1e30f;
#pragma unroll
            for (int j = 0; j < 4; j++) {
                int kj = kv0 + tx4 + j;
                s[i][j] = (kj <= qi) ? s[i][j] * scale : -1e30f;
                mx = fmaxf(mx, s[i][j]);
            }
            red[(ty4 + i) * 16 + tx] = mx;
        }
        __syncthreads();

        if (tid < 64) {
            float m  = rowm[tid];
            float mt = -1e30f;
#pragma unroll
            for (int x = 0; x < 16; x++) mt = fmaxf(mt, red[tid * 16 + x]);
            float mn = fmaxf(m, mt);
            float al = __expf(m - mn);
            rowa[tid] = al;
            rowl[tid] *= al;
            rowm[tid] = mn;
        }
        __syncthreads();

#pragma unroll
        for (int i = 0; i < 4; i++) {
            int r = ty4 + i;
            float m = rowm[r];
            float sum = 0.f;
#pragma unroll
            for (int j = 0; j < 4; j++) {
                float p = __expf(s[i][j] - m);
                Ps[r * 64 + tx4 + j] = p;
                sum += p;
            }
            red[r * 16 + tx] = sum;
            float al = rowa[r];
#pragma unroll
            for (int c = 0; c < 8; c++) acc[i][c] *= al;
        }
        __syncthreads();

        if (tid < 64) {
            float sum = 0.f;
#pragma unroll
            for (int x = 0; x < 16; x++) sum += red[tid * 16 + x];
            rowl[tid] += sum;
        }

#pragma unroll 2
        for (int j = 0; j < 64; j++) {
            float p0 = Ps[(ty4 + 0) * 64 + j];
            float p1 = Ps[(ty4 + 1) * 64 + j];
            float p2 = Ps[(ty4 + 2) * 64 + j];
            float p3 = Ps[(ty4 + 3) * 64 + j];
            float4 va = *(float4*)&Vs[j * 128 + tx4];
            float4 vb = *(float4*)&Vs[j * 128 + 64 + tx4];
            acc[0][0] += p0 * va.x; acc[0][1] += p0 * va.y; acc[0][2] += p0 * va.z; acc[0][3] += p0 * va.w;
            acc[1][0] += p1 * va.x; acc[1][1] += p1 * va.y; acc[1][2] += p1 * va.z; acc[1][3] += p1 * va.w;
            acc[2][0] += p2 * va.x; acc[2][1] += p2 * va.y; acc[2][2] += p2 * va.z; acc[2][3] += p2 * va.w;
            acc[3][0] += p3 * va.x; acc[3][1] += p3 * va.y; acc[3][2] += p3 * va.z; acc[3][3] += p3 * va.w;
            acc[0][4] += p0 * vb.x; acc[0][5] += p0 * vb.y; acc[0][6] += p0 * vb.z; acc[0][7] += p0 * vb.w;
            acc[1][4] += p1 * vb.x; acc[1][5] += p1 * vb.y; acc[1][6] += p1 * vb.z; acc[1][7] += p1 * vb.w;
            acc[2][4] += p2 * vb.x; acc[2][5] += p2 * vb.y; acc[2][6] += p2 * vb.z; acc[2][7] += p2 * vb.w;
            acc[3][4] += p3 * vb.x; acc[3][5] += p3 * vb.y; acc[3][6] += p3 * vb.z; acc[3][7] += p3 * vb.w;
        }
    }
    __syncthreads();

#pragma unroll
    for (int i = 0; i < 4; i++) {
        int r = ty4 + i;
        float inv = 1.f / rowl[r];
        size_t obase = (size_t)(b * SEQ + q0 + r) * ((size_t)NH * HD) + h * HD;
        *(float4*)&O[obase + tx4] =
            make_float4(acc[i][0] * inv, acc[i][1] * inv, acc[i][2] * inv, acc[i][3] * inv);
        *(float4*)&O[obase + 64 + tx4] =
            make_float4(acc[i][4] * inv, acc[i][5] * inv, acc[i][6] * inv, acc[i][7] * inv);
    }
}

// ---------------------------------------------------------------------------
extern "C" void kernel_launch(void* const* d_in, const int* in_sizes, int n_in,
                              void* d_out, int out_size) {
    const float* hidden = (const float*)d_in[0];
    const float* cosb   = (const float*)d_in[1];
    const float* sinb   = (const float*)d_in[2];
    const float* w_qkv  = (const float*)d_in[3];
    const float* w_o    = (const float*)d_in[4];
    const float* kc_in  = (const float*)d_in[5];
    const float* vc_in  = (const float*)d_in[6];
    const int*   slots  = (const int*)d_in[7];

    float* out    = (float*)d_out;
    float* kc_out = out + (size_t)T_TOK * HIDDEN_;
    float* vc_out = kc_out + (size_t)NUM_SLOTS_ * KVH_ * HD;

    float *qkv, *attn;
    cudaGetSymbolAddress((void**)&qkv, g_qkv);
    cudaGetSymbolAddress((void**)&attn, g_attn);

    const size_t cache_bytes = sizeof(float) * (size_t)NUM_SLOTS_ * KVH_ * HD;
    cudaMemcpyAsync(kc_out, kc_in, cache_bytes, cudaMemcpyDeviceToDevice);
    cudaMemcpyAsync(vc_out, vc_in, cache_bytes, cudaMemcpyDeviceToDevice);

    // QKV projection (tf32 tensor cores)
    tf32gemm_nt<<<dim3(QKV_N / 128, T_TOK / 128), 256>>>(hidden, w_qkv, qkv,
                                                         T_TOK, QKV_N, HIDDEN_);
    // RoPE + cache scatter
    rope_scatter<<<T_TOK, 256>>>(cosb, sinb, slots, kc_out, vc_out);

    // Flash attention (fp32 SIMT — next optimization target)
    int smem = (128 * 65 * 2 + 64 * 128 + 64 * 64 + 64 * 3 + 64 * 16) * sizeof(float);
    cudaFuncSetAttribute(flash_attn, cudaFuncAttributeMaxDynamicSharedMemorySize, smem);
    flash_attn<<<dim3(SEQ / 64, NH, NB), 256, smem>>>(attn);

    // Output projection (tf32 tensor cores)
    tf32gemm_nt<<<dim3(HIDDEN_ / 128, T_TOK / 128), 256>>>(attn, w_o, out,
                                                           T_TOK, HIDDEN_, HIDDEN_);
}